// round 16
// baseline (speedup 1.0000x reference)
#include <cuda_runtime.h>
#include <cuda_fp16.h>
#include <cstdint>

#define D_MODEL 2048
#define NHEADS  16
#define HDIM    128
#define BATCH   4
#define SEQ     2048
#define BHT     (BATCH * NHEADS)   // 64
#define MROWS   (BATCH * SEQ)      // 8192

// ---------------- scratch (device globals: no cudaMalloc allowed) -----------
__device__ __half g_Q[BHT * SEQ * HDIM];   // [bh][t][hd]
__device__ __half g_K[BHT * SEQ * HDIM];
__device__ __half g_V[BHT * SEQ * HDIM];
__device__ __half g_C[MROWS * D_MODEL];    // ctx [b*T+t][h*hd+d]
__device__ __half g_XH[MROWS * D_MODEL];   // X as fp16
__device__ __half g_WH[4 * D_MODEL * D_MODEL];  // W^T [n][k] fp16

// ---------------- helpers ----------------------------------------------------
__device__ __forceinline__ uint32_t smem_u32(const void* p) {
    uint32_t a;
    asm("{ .reg .u64 t; cvta.to.shared.u64 t, %1; cvt.u32.u64 %0, t; }"
        : "=r"(a) : "l"(p));
    return a;
}

__device__ __forceinline__ void cp16(uint32_t dst, const void* src) {
    asm volatile("cp.async.cg.shared.global [%0], [%1], 16;"
                 :: "r"(dst), "l"(src) : "memory");
}
#define CP_COMMIT() asm volatile("cp.async.commit_group;" ::: "memory")
#define CP_WAIT(n)  asm volatile("cp.async.wait_group %0;" :: "n"(n) : "memory")

__device__ __forceinline__ void ldsm4(unsigned* r, uint32_t addr) {
    asm volatile("ldmatrix.sync.aligned.m8n8.x4.shared.b16 {%0,%1,%2,%3}, [%4];"
                 : "=r"(r[0]), "=r"(r[1]), "=r"(r[2]), "=r"(r[3]) : "r"(addr));
}
__device__ __forceinline__ void ldsm4t(unsigned* r, uint32_t addr) {
    asm volatile("ldmatrix.sync.aligned.m8n8.x4.trans.shared.b16 {%0,%1,%2,%3}, [%4];"
                 : "=r"(r[0]), "=r"(r[1]), "=r"(r[2]), "=r"(r[3]) : "r"(addr));
}

// fp16 mma m16n8k16, fp32 accumulate
__device__ __forceinline__ void mma16(float* c,
                                      unsigned a0, unsigned a1, unsigned a2, unsigned a3,
                                      unsigned b0, unsigned b1) {
    asm volatile(
        "mma.sync.aligned.m16n8k16.row.col.f32.f16.f16.f32 "
        "{%0,%1,%2,%3},{%4,%5,%6,%7},{%8,%9},{%0,%1,%2,%3};"
        : "+f"(c[0]), "+f"(c[1]), "+f"(c[2]), "+f"(c[3])
        : "r"(a0), "r"(a1), "r"(a2), "r"(a3), "r"(b0), "r"(b1));
}

// ---------------- pre-passes --------------------------------------------------
__global__ void cvt_xh(const float* __restrict__ X) {
    size_t i = ((size_t)blockIdx.x * 256 + threadIdx.x) * 4;
    float4 v = *(const float4*)(X + i);
    *(__half2*)&g_XH[i]     = __floats2half2_rn(v.x, v.y);
    *(__half2*)&g_XH[i + 2] = __floats2half2_rn(v.z, v.w);
}

// WH[n][k] = fp16(W[k][n]) for the 4 weight matrices (z-indexed)
__global__ void transpose_w4h(const float* __restrict__ w0, const float* __restrict__ w1,
                              const float* __restrict__ w2, const float* __restrict__ w3) {
    __shared__ float tile[32][33];
    const float* W = (blockIdx.z == 0) ? w0 : (blockIdx.z == 1) ? w1
                   : (blockIdx.z == 2) ? w2 : w3;
    __half* WT = g_WH + (size_t)blockIdx.z * D_MODEL * D_MODEL;
    int bx = blockIdx.x * 32;   // n
    int by = blockIdx.y * 32;   // k
    int tx = threadIdx.x, ty = threadIdx.y;
#pragma unroll
    for (int i = 0; i < 32; i += 8)
        tile[ty + i][tx] = W[(size_t)(by + ty + i) * D_MODEL + bx + tx];
    __syncthreads();
#pragma unroll
    for (int i = 0; i < 32; i += 8)
        WT[(size_t)(bx + ty + i) * D_MODEL + by + tx] = __float2half_rn(tile[tx][ty + i]);
}

// ---------------- GEMM: C[M,N] = A[M,K] @ W[K,N] + bias ----------------------
// CTA 128x256, 256 threads (8 warps 2x4), warp tile 64x64 (mt=4, nt=8):
// 8 LDSM per 32 mma per k16-step (2x operand reuse vs 32x64 warp tile).
// K-chunk 64, 3-stage cp.async ring (prefetch 2), fragment double-buffer.
// 1 CTA/SM, <=255 regs.
#define TBM 128
#define TBN 256
#define RSTB 144
#define STG_BYTES ((TBM + TBN) * RSTB)       // 55296
#define GEMM_SMEM (3 * STG_BYTES)            // 165888

template <int MODE>
__global__ void __launch_bounds__(256, 1)
gemm_h(const __half* __restrict__ A,
       const float* __restrict__ b0p, const float* __restrict__ b1p,
       const float* __restrict__ b2p, float* __restrict__ outf) {
    extern __shared__ char smc[];
    const int tid = threadIdx.x, lane = tid & 31, wid = tid >> 5;
    const int wm = wid >> 2, wn = wid & 3;     // 2 x 4 warp grid, warp 64x64
    const int q4 = lane & 3, l4 = lane >> 2;
    const int m0 = blockIdx.y * TBM, n0 = blockIdx.x * TBN;

    const int z = (MODE == 0) ? blockIdx.z : 3;
    const __half* Bg = g_WH + (size_t)z * D_MODEL * D_MODEL + (size_t)n0 * D_MODEL;
    const float* bias = (MODE == 1) ? b0p
                        : ((z == 0) ? b0p : (z == 1) ? b1p : b2p);
    const __half* Ag = A + (size_t)m0 * D_MODEL;

    float acc[4][8][4];
#pragma unroll
    for (int mt = 0; mt < 4; mt++)
#pragma unroll
        for (int nt = 0; nt < 8; nt++)
#pragma unroll
            for (int e = 0; e < 4; e++) acc[mt][nt][e] = 0.f;

    const uint32_t aoff = (wm * 64 + (lane & 15)) * RSTB + (lane >> 4) * 16;
    const uint32_t boff = TBM * RSTB
        + (wn * 64 + (lane & 7) + ((lane >> 4) & 1) * 8) * RSTB
        + ((lane >> 3) & 1) * 16;
    const uint32_t smbase = smem_u32(smc);

    const int NK = D_MODEL / 64;   // 32 chunks of k64

    auto stage_in = [&](int kt) {
        const uint32_t sb = smbase + (uint32_t)(kt % 3) * STG_BYTES;
        const int ko = kt * 64;
#pragma unroll
        for (int i = 0; i < 4; i++) {               // A: 128 rows x 8 x 16B
            int lin = tid + i * 256; int r = lin >> 3, c = lin & 7;
            cp16(sb + r * RSTB + c * 16, Ag + (size_t)r * D_MODEL + ko + c * 8);
        }
#pragma unroll
        for (int i = 0; i < 8; i++) {               // B: 256 rows x 8 x 16B
            int lin = tid + i * 256; int r = lin >> 3, c = lin & 7;
            cp16(sb + TBM * RSTB + r * RSTB + c * 16,
                 Bg + (size_t)r * D_MODEL + ko + c * 8);
        }
        CP_COMMIT();
    };

    stage_in(0);
    stage_in(1);

    for (int kt = 0; kt < NK; kt++) {
        if (kt + 1 < NK) { CP_WAIT(1); } else { CP_WAIT(0); }
        __syncthreads();
        if (kt + 2 < NK) stage_in(kt + 2);

        const uint32_t sb = smbase + (uint32_t)(kt % 3) * STG_BYTES;
        const uint32_t aaddr = sb + aoff;
        const uint32_t baddr = sb + boff;

        unsigned af[2][4][4], bf[2][4][4];
#pragma unroll
        for (int mt = 0; mt < 4; mt++)
            ldsm4(af[0][mt], aaddr + mt * (16 * RSTB));
#pragma unroll
        for (int p = 0; p < 4; p++)
            ldsm4(bf[0][p], baddr + p * (16 * RSTB));

#pragma unroll
        for (int ks = 0; ks < 4; ks++) {
            const int cur = ks & 1, nxt = cur ^ 1;
            if (ks < 3) {
#pragma unroll
                for (int mt = 0; mt < 4; mt++)
                    ldsm4(af[nxt][mt], aaddr + mt * (16 * RSTB) + (ks + 1) * 32);
#pragma unroll
                for (int p = 0; p < 4; p++)
                    ldsm4(bf[nxt][p], baddr + p * (16 * RSTB) + (ks + 1) * 32);
            }
#pragma unroll
            for (int mt = 0; mt < 4; mt++)
#pragma unroll
                for (int nt = 0; nt < 8; nt++)
                    mma16(acc[mt][nt],
                          af[cur][mt][0], af[cur][mt][1], af[cur][mt][2], af[cur][mt][3],
                          bf[cur][nt >> 1][(nt & 1) * 2], bf[cur][nt >> 1][(nt & 1) * 2 + 1]);
        }
    }

    __half* dsth = (MODE == 0) ? ((z == 0) ? g_Q : (z == 1) ? g_K : g_V) : (__half*)0;
#pragma unroll
    for (int mt = 0; mt < 4; mt++) {
#pragma unroll
        for (int nt = 0; nt < 8; nt++) {
            int n = n0 + wn * 64 + nt * 8 + 2 * q4;
            float bz0 = bias[n], bz1 = bias[n + 1];
            int r0 = m0 + wm * 64 + mt * 16 + l4;
            int r1 = r0 + 8;
            float c00 = acc[mt][nt][0] + bz0, c01 = acc[mt][nt][1] + bz1;
            float c10 = acc[mt][nt][2] + bz0, c11 = acc[mt][nt][3] + bz1;
            if (MODE == 0) {
                int h = n >> 7, d = n & 127;
                int b0i = r0 >> 11, t0 = r0 & 2047;
                int b1i = r1 >> 11, t1 = r1 & 2047;
                *(__half2*)&dsth[((size_t)(b0i * NHEADS + h) * SEQ + t0) * HDIM + d] =
                    __floats2half2_rn(c00, c01);
                *(__half2*)&dsth[((size_t)(b1i * NHEADS + h) * SEQ + t1) * HDIM + d] =
                    __floats2half2_rn(c10, c11);
            } else {
                *(float2*)&outf[(size_t)r0 * D_MODEL + n] = make_float2(c00, c01);
                *(float2*)&outf[(size_t)r1 * D_MODEL + n] = make_float2(c10, c11);
            }
        }
    }
}

// ---------------- attention: 128x128 flash, unnormalized softmax -------------
// ABN=128: half the key-tiles of R15 -> half the barriers/CP_WAITs.
// 2-stage K/V cp.async ring (prefetch 1) + fragment double-buffering.
// p = exp(s*scale - 8); shift cancels in the final divide.
#define ABM 128
#define ABN 128
#define QRSB 272    // Q/K/V/P row bytes: 256B data + 16B pad
#define KV_STG (ABN * QRSB)   // 34816 per K (or V) stage
#define SM_SCALE 0.08838834764831845f  // 1/sqrt(128)
#define P_SHIFT 8.0f

// Q + 2*K + 2*V + P + rs
#define ATT_SMEM_BYTES (ABM * QRSB + 4 * KV_STG + ABM * QRSB + 1024)

__global__ void __launch_bounds__(256, 1) attention_kernel() {
    extern __shared__ char smc[];
    const uint32_t base = smem_u32(smc);
    const uint32_t qb_  = base;                          // Q: 128*272
    const uint32_t kb0_ = qb_ + ABM * QRSB;              // K stages: 2*128*272
    const uint32_t vb0_ = kb0_ + 2 * KV_STG;             // V stages: 2*128*272
    const uint32_t sb_  = vb0_ + 2 * KV_STG;             // P: 128*272
    __half* SsH = (__half*)(smc + (ABM * QRSB + 4 * KV_STG));
    float* rsf  = (float*)(smc + (ABM * QRSB + 4 * KV_STG + ABM * QRSB));

    const int tid  = threadIdx.x;
    const int lane = tid & 31;
    const int wid  = tid >> 5;
    const int wm   = wid >> 1;         // 0..3 -> 32 query rows
    const int wn   = wid & 1;          // 0..1
    const int q4   = lane & 3, l4 = lane >> 2;

    const int qb = (gridDim.x - 1) - blockIdx.x;   // heavy blocks first
    const int bh = blockIdx.y;
    const int q0 = qb * ABM;

    // LDSM lane byte-offsets (stage-relative for K/V)
    const uint32_t qa_off = (wm * 32 + (lane & 15)) * QRSB + (lane >> 4) * 16;
    const uint32_t kb_off = (wn * 64 + (lane & 7) + ((lane >> 4) & 1) * 8) * QRSB
                            + ((lane >> 3) & 1) * 16;
    const uint32_t sa_off = (wm * 32 + (lane & 15)) * QRSB + (lane >> 4) * 16;
    const uint32_t vb_off = ((lane & 7) + ((lane >> 3) & 1) * 8) * QRSB
                            + wn * 128 + ((lane >> 4) & 1) * 16;

    const int njt = qb + 1;

    // K/V stage loader for key-tile j -> slot j&1 (one commit group)
    auto att_stage = [&](int j) {
        const int k0 = j * ABN;
        const __half* Kg = g_K + ((size_t)bh * SEQ + k0) * HDIM;
        const __half* Vg = g_V + ((size_t)bh * SEQ + k0) * HDIM;
        const uint32_t kb = kb0_ + (uint32_t)(j & 1) * KV_STG;
        const uint32_t vb = vb0_ + (uint32_t)(j & 1) * KV_STG;
#pragma unroll
        for (int i = 0; i < 8; i++) {
            int lin = tid + i * 256;
            int r = lin >> 4, c = lin & 15;
            cp16(kb + r * QRSB + c * 16, Kg + (size_t)r * HDIM + c * 8);
            cp16(vb + r * QRSB + c * 16, Vg + (size_t)r * HDIM + c * 8);
        }
        CP_COMMIT();
    };

    // Q tile loads (committed together with stage 0)
    const __half* Qg = g_Q + ((size_t)bh * SEQ + q0) * HDIM;
#pragma unroll
    for (int i = 0; i < 8; i++) {
        int lin = tid + i * 256;
        int r = lin >> 4, c = lin & 15;
        cp16(qb_ + r * QRSB + c * 16, Qg + (size_t)r * HDIM + c * 8);
    }
    att_stage(0);   // commit covers Q + K0/V0

    float oacc[2][8][4];
#pragma unroll
    for (int mt = 0; mt < 2; mt++)
#pragma unroll
        for (int j = 0; j < 8; j++)
#pragma unroll
            for (int e = 0; e < 4; e++) oacc[mt][j][e] = 0.f;
    float rsum[2][2] = {{0.f, 0.f}, {0.f, 0.f}};

    const int rl0 = wm * 32 + l4;
    const int rl1 = rl0 + 16;

    for (int j = 0; j < njt; j++) {
        const int k0 = j * ABN;
        CP_WAIT(0);           // stage j (and Q on j=0) resident
        __syncthreads();      // PV(j-1) done -> safe to refill slot (j+1)&1
        if (j + 1 < njt) att_stage(j + 1);   // overlaps tile j's compute

        const uint32_t kb = kb0_ + (uint32_t)(j & 1) * KV_STG;
        const uint32_t vb = vb0_ + (uint32_t)(j & 1) * KV_STG;

        // ---- S = Q K^T : warp 32 rows x 64 keys, 8 k16-steps ----
        float s[2][8][4];
#pragma unroll
        for (int mt = 0; mt < 2; mt++)
#pragma unroll
            for (int nt = 0; nt < 8; nt++)
#pragma unroll
                for (int e = 0; e < 4; e++) s[mt][nt][e] = 0.f;

        {
            unsigned af[2][2][4], bf[2][4][4];
            ldsm4(af[0][0], qb_ + qa_off);
            ldsm4(af[0][1], qb_ + qa_off + 16 * QRSB);
#pragma unroll
            for (int p = 0; p < 4; p++)
                ldsm4(bf[0][p], kb + kb_off + p * (16 * QRSB));
#pragma unroll
            for (int ks = 0; ks < 8; ks++) {
                const int cur = ks & 1, nxt = cur ^ 1;
                if (ks < 7) {
                    ldsm4(af[nxt][0], qb_ + qa_off + (ks + 1) * 32);
                    ldsm4(af[nxt][1], qb_ + qa_off + 16 * QRSB + (ks + 1) * 32);
#pragma unroll
                    for (int p = 0; p < 4; p++)
                        ldsm4(bf[nxt][p], kb + kb_off + p * (16 * QRSB) + (ks + 1) * 32);
                }
#pragma unroll
                for (int nt = 0; nt < 8; nt++) {
                    unsigned b0 = bf[cur][nt >> 1][(nt & 1) * 2];
                    unsigned b1 = bf[cur][nt >> 1][(nt & 1) * 2 + 1];
                    mma16(s[0][nt], af[cur][0][0], af[cur][0][1], af[cur][0][2], af[cur][0][3], b0, b1);
                    mma16(s[1][nt], af[cur][1][0], af[cur][1][1], af[cur][1][2], af[cur][1][3], b0, b1);
                }
            }
        }

        // ---- mask + exp (shifted) + write P (fp16) ----
        const bool diag = (j == qb);
#pragma unroll
        for (int mt = 0; mt < 2; mt++) {
            const int rb = (mt == 0) ? rl0 : rl1;
#pragma unroll
            for (int nt = 0; nt < 8; nt++) {
                int cl = wn * 64 + nt * 8 + 2 * q4;
                float p00 = __expf(s[mt][nt][0] * SM_SCALE - P_SHIFT);
                float p01 = __expf(s[mt][nt][1] * SM_SCALE - P_SHIFT);
                float p10 = __expf(s[mt][nt][2] * SM_SCALE - P_SHIFT);
                float p11 = __expf(s[mt][nt][3] * SM_SCALE - P_SHIFT);
                if (diag) {
                    int cg = k0 + cl;
                    int rg0 = q0 + rb;
                    int rg1 = rg0 + 8;
                    if (cg > rg0)     p00 = 0.f;
                    if (cg + 1 > rg0) p01 = 0.f;
                    if (cg > rg1)     p10 = 0.f;
                    if (cg + 1 > rg1) p11 = 0.f;
                }
                rsum[mt][0] += p00 + p01;
                rsum[mt][1] += p10 + p11;
                *(__half2*)&SsH[rb * (QRSB / 2) + cl]       = __floats2half2_rn(p00, p01);
                *(__half2*)&SsH[(rb + 8) * (QRSB / 2) + cl] = __floats2half2_rn(p10, p11);
            }
        }
        __syncthreads();

        // ---- O += P V : warp 32 rows x 64 cols, 8 k16-steps over 128 keys ----
        {
            unsigned af[2][2][4], bv[2][4][4];
            ldsm4(af[0][0], sb_ + sa_off);
            ldsm4(af[0][1], sb_ + sa_off + 16 * QRSB);
#pragma unroll
            for (int p = 0; p < 4; p++)
                ldsm4t(bv[0][p], vb + vb_off + p * 32);
#pragma unroll
            for (int ks = 0; ks < 8; ks++) {
                const int cur = ks & 1, nxt = cur ^ 1;
                if (ks < 7) {
                    ldsm4(af[nxt][0], sb_ + sa_off + (ks + 1) * 32);
                    ldsm4(af[nxt][1], sb_ + sa_off + 16 * QRSB + (ks + 1) * 32);
#pragma unroll
                    for (int p = 0; p < 4; p++)
                        ldsm4t(bv[nxt][p], vb + vb_off + (ks + 1) * 16 * QRSB + p * 32);
                }
#pragma unroll
                for (int nt = 0; nt < 8; nt++) {
                    unsigned b0 = bv[cur][nt >> 1][(nt & 1) * 2];
                    unsigned b1 = bv[cur][nt >> 1][(nt & 1) * 2 + 1];
                    mma16(oacc[0][nt], af[cur][0][0], af[cur][0][1], af[cur][0][2], af[cur][0][3], b0, b1);
                    mma16(oacc[1][nt], af[cur][1][0], af[cur][1][1], af[cur][1][2], af[cur][1][3], b0, b1);
                }
            }
        }
    }

    // ---- reduce row sums across quad + across wn ----
#pragma unroll
    for (int mt = 0; mt < 2; mt++)
#pragma unroll
        for (int h = 0; h < 2; h++) {
            rsum[mt][h] += __shfl_xor_sync(0xffffffffu, rsum[mt][h], 1);
            rsum[mt][h] += __shfl_xor_sync(0xffffffffu, rsum[mt][h], 2);
        }
    if (q4 == 0) {
        rsf[wn * 128 + rl0]     = rsum[0][0];
        rsf[wn * 128 + rl0 + 8] = rsum[0][1];
        rsf[wn * 128 + rl1]     = rsum[1][0];
        rsf[wn * 128 + rl1 + 8] = rsum[1][1];
    }
    __syncthreads();

    // ---- write ctx (fp16) ----
    const int b = bh >> 4, h = bh & 15;
#pragma unroll
    for (int mt = 0; mt < 2; mt++) {
        const int rb = (mt == 0) ? rl0 : rl1;
        float inv0 = 1.f / (rsf[rb] + rsf[128 + rb]);
        float inv1 = 1.f / (rsf[rb + 8] + rsf[128 + rb + 8]);
        const int t0 = q0 + rb;
        __half* dst0 = g_C + ((size_t)(b * SEQ + t0) * D_MODEL) + h * HDIM;
        __half* dst1 = g_C + ((size_t)(b * SEQ + t0 + 8) * D_MODEL) + h * HDIM;
#pragma unroll
        for (int nt = 0; nt < 8; nt++) {
            int c = wn * 64 + nt * 8 + 2 * q4;
            *(__half2*)(dst0 + c) = __floats2half2_rn(oacc[mt][nt][0] * inv0,
                                                      oacc[mt][nt][1] * inv0);
            *(__half2*)(dst1 + c) = __floats2half2_rn(oacc[mt][nt][2] * inv1,
                                                      oacc[mt][nt][3] * inv1);
        }
    }
}

// ---------------- launch -----------------------------------------------------
extern "C" void kernel_launch(void* const* d_in, const int* in_sizes, int n_in,
                              void* d_out, int out_size) {
    const float* X    = (const float*)d_in[0];
    // d_in[1] = additive causal mask, implemented analytically
    const float* wq_w = (const float*)d_in[2];
    const float* wq_b = (const float*)d_in[3];
    const float* wk_w = (const float*)d_in[4];
    const float* wk_b = (const float*)d_in[5];
    const float* wv_w = (const float*)d_in[6];
    const float* wv_b = (const float*)d_in[7];
    const float* wo_w = (const float*)d_in[8];
    const float* wo_b = (const float*)d_in[9];

    void *pc, *pxh;
    cudaGetSymbolAddress(&pc, g_C);
    cudaGetSymbolAddress(&pxh, g_XH);
    const __half* XH = (const __half*)pxh;

    cudaFuncSetAttribute(gemm_h<0>,
                         cudaFuncAttributeMaxDynamicSharedMemorySize, GEMM_SMEM);
    cudaFuncSetAttribute(gemm_h<1>,
                         cudaFuncAttributeMaxDynamicSharedMemorySize, GEMM_SMEM);
    cudaFuncSetAttribute(attention_kernel,
                         cudaFuncAttributeMaxDynamicSharedMemorySize, ATT_SMEM_BYTES);

    cvt_xh<<<(MROWS * D_MODEL) / (256 * 4), 256>>>(X);
    transpose_w4h<<<dim3(64, 64, 4), dim3(32, 8)>>>(wq_w, wk_w, wv_w, wo_w);

    // fused QKV: grid.z selects Q/K/V
    gemm_h<0><<<dim3(D_MODEL / TBN, MROWS / TBM, 3), 256, GEMM_SMEM>>>(
        XH, wq_b, wk_b, wv_b, nullptr);

    attention_kernel<<<dim3(SEQ / ABM, BHT), 256, ATT_SMEM_BYTES>>>();

    gemm_h<1><<<dim3(D_MODEL / TBN, MROWS / TBM, 1), 256, GEMM_SMEM>>>(
        (const __half*)pc, wo_b, nullptr, nullptr, (float*)d_out);
}